// round 8
// baseline (speedup 1.0000x reference)
#include <cuda_runtime.h>
#include <math.h>
#include <float.h>

#define D_    1024
#define H_    16
#define HK_   8
#define HD_   64
#define FF_   3072
#define S_    1024
#define B_    4
#define TOK_  4096   // B*S
#define L_    4
#define WIN_  12

// ---------------- scratch (no allocations allowed) ----------------
__device__ float g_h   [TOK_ * D_];
__device__ float g_n   [TOK_ * D_];
__device__ float g_q   [TOK_ * H_  * HD_];
__device__ float g_k   [TOK_ * HK_ * HD_];
__device__ float g_v   [TOK_ * HK_ * HD_];
__device__ float g_att [TOK_ * H_  * HD_];
__device__ float g_gate[TOK_ * FF_];
__device__ float g_up  [TOK_ * FF_];

// ---------------- helpers ----------------
__device__ __forceinline__ unsigned f2tf(float x) {
    unsigned r;
    asm("cvt.rna.tf32.f32 %0, %1;" : "=r"(r) : "f"(x));
    return r;
}
__device__ __forceinline__ float tfr(float x) { return __uint_as_float(f2tf(x)); }
__device__ __forceinline__ void cpasync16(float* dst_smem, const float* src_gmem) {
    unsigned d = (unsigned)__cvta_generic_to_shared(dst_smem);
    asm volatile("cp.async.cg.shared.global [%0], [%1], 16;"
                 :: "r"(d), "l"(src_gmem));
}
#define CP_COMMIT() asm volatile("cp.async.commit_group;")
#define CP_WAIT0()  asm volatile("cp.async.wait_group 0;")

#define MMA_TF32(acc, a, b)                                              \
    asm volatile(                                                        \
        "mma.sync.aligned.m16n8k8.row.col.f32.tf32.tf32.f32 "            \
        "{%0,%1,%2,%3}, {%4,%5,%6,%7}, {%8,%9}, {%0,%1,%2,%3};"          \
        : "+f"((acc)[0]), "+f"((acc)[1]), "+f"((acc)[2]), "+f"((acc)[3]) \
        : "r"((a)[0]), "r"((a)[1]), "r"((a)[2]), "r"((a)[3]),            \
          "r"((b)[0]), "r"((b)[1]))

// ---------------- rmsnorm over 1024 cols, 1 block per row ----------------
__global__ void rmsnorm_kernel(const float* __restrict__ x,
                               const float* __restrict__ w,
                               float* __restrict__ out) {
    int row = blockIdx.x;
    const float* xr = x + (size_t)row * D_;
    int t = threadIdx.x;               // 256 threads, 4 floats each
    float4 v = *(const float4*)(xr + t * 4);
    float ss = v.x * v.x + v.y * v.y + v.z * v.z + v.w * v.w;
    #pragma unroll
    for (int o = 16; o; o >>= 1) ss += __shfl_xor_sync(0xffffffffu, ss, o);
    __shared__ float sh[8];
    if ((t & 31) == 0) sh[t >> 5] = ss;
    __syncthreads();
    float tot = 0.f;
    #pragma unroll
    for (int i = 0; i < 8; i++) tot += sh[i];
    float scale = rsqrtf(tot * (1.0f / D_) + 1e-6f);
    float4 wv = *(const float4*)(w + t * 4);
    float4 o4;
    o4.x = v.x * scale * wv.x;
    o4.y = v.y * scale * wv.y;
    o4.z = v.z * scale * wv.z;
    o4.w = v.w * scale * wv.w;
    *(float4*)(out + (size_t)row * D_ + t * 4) = o4;
}

// ---------------- TF32 tensor-core GEMM core (cp.async, BK=32, dynamic smem) ----------------
// Block tile 128x128, BK=32, 256 threads (8 warps, 2x4). Warp tile 64x32.
// A smem row-major stride 36 (conflict-free frags), B smem stride 136.
#define AST2 36
#define BST2 136
#define GSMEM_BYTES ((2 * 128 * AST2 + 2 * 32 * BST2) * 4)   // 71680
template <bool ACC>
__device__ __forceinline__ void gemm_core(const float* __restrict__ A,
                                          const float* __restrict__ B,
                                          float* __restrict__ C,
                                          int N, int K, int bx, int by) {
    extern __shared__ float smem[];
    float* As = smem;                        // 2 stages x 128 x AST2
    float* Bs = smem + 2 * 128 * AST2;       // 2 stages x 32 x BST2
    const int ASTAGE = 128 * AST2;
    const int BSTAGE = 32 * BST2;

    int tid = threadIdx.x;
    int lane = tid & 31, wid = tid >> 5;
    int wr = wid >> 2;          // 0..1  (64-row slab)
    int wc = wid & 3;           // 0..3  (32-col slab)
    int tg = lane & 3;          // k index within fragment
    int grp = lane >> 2;        // m/n index within fragment

    const float* Ag = A + (size_t)(by * 128) * K;
    const float* Bg = B + bx * 128;

    // cp.async plan (per thread, per stage): A row tid>>1, 16 floats at col 16*(tid&1)
    //                                        B row tid>>3, 16 floats at col 16*(tid&7)
    int arow = tid >> 1, acol = (tid & 1) * 16;
    int brow = tid >> 3, bcol = (tid & 7) * 16;

    float acc[4][4][4];
    #pragma unroll
    for (int i = 0; i < 4; i++)
        #pragma unroll
        for (int j = 0; j < 4; j++)
            #pragma unroll
            for (int c = 0; c < 4; c++) acc[i][j][c] = 0.f;

    // prologue: stage 0
    {
        const float* ag = Ag + (size_t)arow * K + acol;
        const float* bg = Bg + (size_t)brow * N + bcol;
        #pragma unroll
        for (int j = 0; j < 4; j++) {
            cpasync16(&As[arow * AST2 + acol + j * 4], ag + j * 4);
            cpasync16(&Bs[brow * BST2 + bcol + j * 4], bg + j * 4);
        }
        CP_COMMIT();
    }

    int nIter = K >> 5;
    for (int it = 0; it < nIter; it++) {
        int cur = it & 1;
        CP_WAIT0();
        __syncthreads();
        if (it + 1 < nIter) {
            int nxt = cur ^ 1;
            int k0n = (it + 1) << 5;
            const float* ag = Ag + (size_t)arow * K + k0n + acol;
            const float* bg = Bg + (size_t)(k0n + brow) * N + bcol;
            #pragma unroll
            for (int j = 0; j < 4; j++) {
                cpasync16(&As[nxt * ASTAGE + arow * AST2 + acol + j * 4], ag + j * 4);
                cpasync16(&Bs[nxt * BSTAGE + brow * BST2 + bcol + j * 4], bg + j * 4);
            }
            CP_COMMIT();
        }

        const float* Ac = As + cur * ASTAGE;
        const float* Bc = Bs + cur * BSTAGE;
        #pragma unroll
        for (int kk = 0; kk < 32; kk += 8) {
            unsigned afr[4][4], bfr[4][2];
            #pragma unroll
            for (int mt = 0; mt < 4; mt++) {
                int m = wr * 64 + mt * 16 + grp;
                afr[mt][0] = f2tf(Ac[m * AST2 + kk + tg]);
                afr[mt][1] = f2tf(Ac[(m + 8) * AST2 + kk + tg]);
                afr[mt][2] = f2tf(Ac[m * AST2 + kk + tg + 4]);
                afr[mt][3] = f2tf(Ac[(m + 8) * AST2 + kk + tg + 4]);
            }
            #pragma unroll
            for (int nt = 0; nt < 4; nt++) {
                int n = wc * 32 + nt * 8 + grp;
                bfr[nt][0] = f2tf(Bc[(kk + tg) * BST2 + n]);
                bfr[nt][1] = f2tf(Bc[(kk + tg + 4) * BST2 + n]);
            }
            #pragma unroll
            for (int mt = 0; mt < 4; mt++)
                #pragma unroll
                for (int nt = 0; nt < 4; nt++)
                    MMA_TF32(acc[mt][nt], afr[mt], bfr[nt]);
        }
        __syncthreads();
    }

    #pragma unroll
    for (int mt = 0; mt < 4; mt++) {
        int row0 = by * 128 + wr * 64 + mt * 16 + grp;
        #pragma unroll
        for (int nt = 0; nt < 4; nt++) {
            int col = bx * 128 + wc * 32 + nt * 8 + tg * 2;
            float* p0 = C + (size_t)row0 * N + col;
            float* p1 = C + (size_t)(row0 + 8) * N + col;
            if (ACC) {
                float2 cc0 = *(float2*)p0, cc1 = *(float2*)p1;
                cc0.x += acc[mt][nt][0]; cc0.y += acc[mt][nt][1];
                cc1.x += acc[mt][nt][2]; cc1.y += acc[mt][nt][3];
                *(float2*)p0 = cc0; *(float2*)p1 = cc1;
            } else {
                *(float2*)p0 = make_float2(acc[mt][nt][0], acc[mt][nt][1]);
                *(float2*)p1 = make_float2(acc[mt][nt][2], acc[mt][nt][3]);
            }
        }
    }
}

template <bool ACC>
__global__ void __launch_bounds__(256, 2)
gemm_tf32(const float* __restrict__ A, const float* __restrict__ B,
          float* __restrict__ C, int N, int K) {
    gemm_core<ACC>(A, B, C, N, K, blockIdx.x, blockIdx.y);
}

__global__ void __launch_bounds__(256, 2)
gemm_qkv(const float* __restrict__ A,
         const float* __restrict__ Wq, const float* __restrict__ Wk,
         const float* __restrict__ Wv,
         float* __restrict__ q, float* __restrict__ k, float* __restrict__ v) {
    int bx = blockIdx.x;
    if (bx < 8)       gemm_core<false>(A, Wq, q, 1024, D_, bx,      blockIdx.y);
    else if (bx < 12) gemm_core<false>(A, Wk, k,  512, D_, bx - 8,  blockIdx.y);
    else              gemm_core<false>(A, Wv, v,  512, D_, bx - 12, blockIdx.y);
}

__global__ void __launch_bounds__(256, 2)
gemm_gateup(const float* __restrict__ A,
            const float* __restrict__ Wg, const float* __restrict__ Wu,
            float* __restrict__ gate, float* __restrict__ up) {
    int bx = blockIdx.x;
    if (bx < 24) gemm_core<false>(A, Wg, gate, FF_, D_, bx,      blockIdx.y);
    else         gemm_core<false>(A, Wu, up,   FF_, D_, bx - 24, blockIdx.y);
}

// ---------------- fused per-head rmsnorm + RoPE for q AND k ----------------
#define LOG2_THETA 19.9315685693241741f
__global__ void qknorm_rope_kernel(float* __restrict__ q, float* __restrict__ k,
                                   const float* __restrict__ qw,
                                   const float* __restrict__ kw) {
    int warp = (blockIdx.x * blockDim.x + threadIdx.x) >> 5;
    int lane = threadIdx.x & 31;
    float* p; const float* w; int token;
    if (warp < TOK_ * H_) {
        p = q + (size_t)warp * HD_; w = qw; token = warp / H_;
    } else {
        int w2 = warp - TOK_ * H_;
        p = k + (size_t)w2 * HD_; w = kw; token = w2 / HK_;
    }
    int s = token & (S_ - 1);
    float a = p[lane], b = p[lane + 32];
    float ss = a * a + b * b;
    #pragma unroll
    for (int o = 16; o; o >>= 1) ss += __shfl_xor_sync(0xffffffffu, ss, o);
    float scale = rsqrtf(ss * (1.0f / HD_) + 1e-6f);
    a *= scale * w[lane];
    b *= scale * w[lane + 32];
    float inv = exp2f(-(float)lane * (LOG2_THETA / 32.0f));
    float ang = (float)s * inv;
    float c = cosf(ang), sn = sinf(ang);
    p[lane]      = a * c - b * sn;
    p[lane + 32] = b * c + a * sn;
}

// ---------------- tensor-core flash attention ----------------
#define QST 68
#define KST 68
#define VST 72
#define PST 36
__global__ void __launch_bounds__(128)
attn_mma_kernel(const float* __restrict__ q, const float* __restrict__ k,
                const float* __restrict__ v, const int* __restrict__ amask,
                float* __restrict__ out, int win) {
    __shared__ float Qs[64 * QST];
    __shared__ float Ks[32 * KST];
    __shared__ float Vs[32 * VST];
    __shared__ float Ps[64 * PST];
    __shared__ float Mk[32];

    int b = blockIdx.z, h = blockIdx.y;
    int q0 = blockIdx.x * 64;
    int kh = h >> 1;
    int tid = threadIdx.x;
    int lane = tid & 31, wid = tid >> 5;
    int tg = lane & 3, grp = lane >> 2;
    int m0 = wid * 16;
    int qpos0 = q0 + m0 + grp;
    int qpos1 = qpos0 + 8;

    for (int i = tid; i < 64 * 16; i += 128) {
        int r = i >> 4, c4 = (i & 15) << 2;
        float4 f = *(const float4*)(q + (size_t)(b * S_ + q0 + r) * (H_ * HD_) + h * HD_ + c4);
        Qs[r * QST + c4 + 0] = tfr(f.x);
        Qs[r * QST + c4 + 1] = tfr(f.y);
        Qs[r * QST + c4 + 2] = tfr(f.z);
        Qs[r * QST + c4 + 3] = tfr(f.w);
    }

    float oacc[8][4];
    #pragma unroll
    for (int i = 0; i < 8; i++)
        #pragma unroll
        for (int j = 0; j < 4; j++) oacc[i][j] = 0.f;
    float mr0 = -1e30f, mr1 = -1e30f, l0 = 0.f, l1 = 0.f;

    int kt_lo = 0, kt_hi = (S_ / 32) - 1;
    if (win >= 0) {
        int lo = q0 - win; if (lo < 0) lo = 0;
        int hi = q0 + 63 + win; if (hi > S_ - 1) hi = S_ - 1;
        kt_lo = lo >> 5; kt_hi = hi >> 5;
    }
    const float scale = 0.125f;

    for (int kt = kt_lo; kt <= kt_hi; kt++) {
        for (int i = tid; i < 32 * 16; i += 128) {
            int r = i >> 4, c4 = (i & 15) << 2;
            size_t off = (size_t)(b * S_ + kt * 32 + r) * (HK_ * HD_) + kh * HD_ + c4;
            float4 fk = *(const float4*)(k + off);
            float4 fv = *(const float4*)(v + off);
            Ks[r * KST + c4 + 0] = tfr(fk.x);
            Ks[r * KST + c4 + 1] = tfr(fk.y);
            Ks[r * KST + c4 + 2] = tfr(fk.z);
            Ks[r * KST + c4 + 3] = tfr(fk.w);
            Vs[r * VST + c4 + 0] = tfr(fv.x);
            Vs[r * VST + c4 + 1] = tfr(fv.y);
            Vs[r * VST + c4 + 2] = tfr(fv.z);
            Vs[r * VST + c4 + 3] = tfr(fv.w);
        }
        if (tid < 32)
            Mk[tid] = (amask[b * S_ + kt * 32 + tid] != 0) ? 0.f : -1e30f;
        __syncthreads();

        float sc[4][4];
        #pragma unroll
        for (int i = 0; i < 4; i++)
            #pragma unroll
            for (int j = 0; j < 4; j++) sc[i][j] = 0.f;
        #pragma unroll
        for (int k8 = 0; k8 < 64; k8 += 8) {
            unsigned a[4];
            a[0] = __float_as_uint(Qs[(m0 + grp) * QST + k8 + tg]);
            a[1] = __float_as_uint(Qs[(m0 + grp + 8) * QST + k8 + tg]);
            a[2] = __float_as_uint(Qs[(m0 + grp) * QST + k8 + tg + 4]);
            a[3] = __float_as_uint(Qs[(m0 + grp + 8) * QST + k8 + tg + 4]);
            #pragma unroll
            for (int nt = 0; nt < 4; nt++) {
                unsigned bb[2];
                bb[0] = __float_as_uint(Ks[(nt * 8 + grp) * KST + k8 + tg]);
                bb[1] = __float_as_uint(Ks[(nt * 8 + grp) * KST + k8 + tg + 4]);
                MMA_TF32(sc[nt], a, bb);
            }
        }

        float v0[8], v1[8];
        #pragma unroll
        for (int nt = 0; nt < 4; nt++) {
            int kc0 = nt * 8 + 2 * tg, kc1 = kc0 + 1;
            int kp0 = kt * 32 + kc0, kp1 = kt * 32 + kc1;
            float mk0 = Mk[kc0], mk1 = Mk[kc1];
            float a0 = sc[nt][0] * scale + mk0;
            float a1 = sc[nt][1] * scale + mk1;
            float b0 = sc[nt][2] * scale + mk0;
            float b1 = sc[nt][3] * scale + mk1;
            if (win >= 0) {
                if (abs(qpos0 - kp0) > win) a0 = -1e30f;
                if (abs(qpos0 - kp1) > win) a1 = -1e30f;
                if (abs(qpos1 - kp0) > win) b0 = -1e30f;
                if (abs(qpos1 - kp1) > win) b1 = -1e30f;
            }
            v0[nt * 2] = a0; v0[nt * 2 + 1] = a1;
            v1[nt * 2] = b0; v1[nt * 2 + 1] = b1;
        }
        float tm0 = -1e30f, tm1 = -1e30f;
        #pragma unroll
        for (int j = 0; j < 8; j++) { tm0 = fmaxf(tm0, v0[j]); tm1 = fmaxf(tm1, v1[j]); }
        tm0 = fmaxf(tm0, __shfl_xor_sync(0xffffffffu, tm0, 1));
        tm0 = fmaxf(tm0, __shfl_xor_sync(0xffffffffu, tm0, 2));
        tm1 = fmaxf(tm1, __shfl_xor_sync(0xffffffffu, tm1, 1));
        tm1 = fmaxf(tm1, __shfl_xor_sync(0xffffffffu, tm1, 2));
        float nm0 = fmaxf(mr0, tm0), nm1 = fmaxf(mr1, tm1);
        float al0 = __expf(mr0 - nm0), al1 = __expf(mr1 - nm1);
        mr0 = nm0; mr1 = nm1;
        float ps0 = 0.f, ps1 = 0.f;
        #pragma unroll
        for (int nt = 0; nt < 4; nt++) {
            float p00 = __expf(v0[nt * 2]     - nm0);
            float p01 = __expf(v0[nt * 2 + 1] - nm0);
            float p10 = __expf(v1[nt * 2]     - nm1);
            float p11 = __expf(v1[nt * 2 + 1] - nm1);
            ps0 += p00 + p01; ps1 += p10 + p11;
            int col = nt * 8 + 2 * tg;
            *(float2*)&Ps[(m0 + grp) * PST + col]     = make_float2(tfr(p00), tfr(p01));
            *(float2*)&Ps[(m0 + grp + 8) * PST + col] = make_float2(tfr(p10), tfr(p11));
        }
        ps0 += __shfl_xor_sync(0xffffffffu, ps0, 1);
        ps0 += __shfl_xor_sync(0xffffffffu, ps0, 2);
        ps1 += __shfl_xor_sync(0xffffffffu, ps1, 1);
        ps1 += __shfl_xor_sync(0xffffffffu, ps1, 2);
        l0 = l0 * al0 + ps0;
        l1 = l1 * al1 + ps1;
        #pragma unroll
        for (int nt = 0; nt < 8; nt++) {
            oacc[nt][0] *= al0; oacc[nt][1] *= al0;
            oacc[nt][2] *= al1; oacc[nt][3] *= al1;
        }
        __syncwarp();

        #pragma unroll
        for (int k8 = 0; k8 < 32; k8 += 8) {
            unsigned a[4];
            a[0] = __float_as_uint(Ps[(m0 + grp) * PST + k8 + tg]);
            a[1] = __float_as_uint(Ps[(m0 + grp + 8) * PST + k8 + tg]);
            a[2] = __float_as_uint(Ps[(m0 + grp) * PST + k8 + tg + 4]);
            a[3] = __float_as_uint(Ps[(m0 + grp + 8) * PST + k8 + tg + 4]);
            #pragma unroll
            for (int nt = 0; nt < 8; nt++) {
                unsigned bb[2];
                bb[0] = __float_as_uint(Vs[(k8 + tg) * VST + nt * 8 + grp]);
                bb[1] = __float_as_uint(Vs[(k8 + tg + 4) * VST + nt * 8 + grp]);
                MMA_TF32(oacc[nt], a, bb);
            }
        }
        __syncthreads();
    }

    float il0 = 1.0f / l0, il1 = 1.0f / l1;
    #pragma unroll
    for (int nt = 0; nt < 8; nt++) {
        int col = h * HD_ + nt * 8 + 2 * tg;
        float* p0 = out + (size_t)(b * S_ + qpos0) * (H_ * HD_) + col;
        float* p1 = out + (size_t)(b * S_ + qpos1) * (H_ * HD_) + col;
        *(float2*)p0 = make_float2(oacc[nt][0] * il0, oacc[nt][1] * il0);
        *(float2*)p1 = make_float2(oacc[nt][2] * il1, oacc[nt][3] * il1);
    }
}

// ---------------- SwiGLU elementwise (vectorized x4) ----------------
__global__ void silu_mul_kernel(float* __restrict__ gate,
                                const float* __restrict__ up, int n4) {
    int i = blockIdx.x * blockDim.x + threadIdx.x;
    if (i < n4) {
        float4 g = *(float4*)(gate + i * 4);
        float4 u = *(const float4*)(up + i * 4);
        g.x = g.x / (1.0f + __expf(-g.x)) * u.x;
        g.y = g.y / (1.0f + __expf(-g.y)) * u.y;
        g.z = g.z / (1.0f + __expf(-g.z)) * u.z;
        g.w = g.w / (1.0f + __expf(-g.w)) * u.w;
        *(float4*)(gate + i * 4) = g;
    }
}

// ---------------- host orchestration ----------------
extern "C" void kernel_launch(void* const* d_in, const int* in_sizes, int n_in,
                              void* d_out, int out_size) {
    const float* x      = (const float*)d_in[0];
    const float* wq     = (const float*)d_in[1];
    const float* wk     = (const float*)d_in[2];
    const float* wv     = (const float*)d_in[3];
    const float* wo     = (const float*)d_in[4];
    const float* qnw    = (const float*)d_in[5];
    const float* knw    = (const float*)d_in[6];
    const float* ln1    = (const float*)d_in[7];
    const float* ln2    = (const float*)d_in[8];
    const float* wg     = (const float*)d_in[9];
    const float* wu     = (const float*)d_in[10];
    const float* wd     = (const float*)d_in[11];
    const float* normw  = (const float*)d_in[12];
    const int*   amask  = (const int*)d_in[13];

    float *h, *n, *q, *k, *v, *att, *gate, *up;
    cudaGetSymbolAddress((void**)&h,    g_h);
    cudaGetSymbolAddress((void**)&n,    g_n);
    cudaGetSymbolAddress((void**)&q,    g_q);
    cudaGetSymbolAddress((void**)&k,    g_k);
    cudaGetSymbolAddress((void**)&v,    g_v);
    cudaGetSymbolAddress((void**)&att,  g_att);
    cudaGetSymbolAddress((void**)&gate, g_gate);
    cudaGetSymbolAddress((void**)&up,   g_up);

    static int smem_set = 0;
    if (!smem_set) {
        cudaFuncSetAttribute(gemm_tf32<true>,
            cudaFuncAttributeMaxDynamicSharedMemorySize, GSMEM_BYTES);
        cudaFuncSetAttribute(gemm_tf32<false>,
            cudaFuncAttributeMaxDynamicSharedMemorySize, GSMEM_BYTES);
        cudaFuncSetAttribute(gemm_qkv,
            cudaFuncAttributeMaxDynamicSharedMemorySize, GSMEM_BYTES);
        cudaFuncSetAttribute(gemm_gateup,
            cudaFuncAttributeMaxDynamicSharedMemorySize, GSMEM_BYTES);
        smem_set = 1;
    }

    cudaMemcpyAsync(h, x, (size_t)TOK_ * D_ * sizeof(float),
                    cudaMemcpyDeviceToDevice, 0);

    dim3 gQKV (16, TOK_ / 128);              // 512 blocks
    dim3 gGU  (48, TOK_ / 128);              // 1536 blocks
    dim3 g1024(D_ / 128, TOK_ / 128);        // 256 blocks
    int ropeWarps = TOK_ * (H_ + HK_);       // 98304 warps

    for (int l = 0; l < L_; l++) {
        const float* wq_l = wq + (size_t)l * D_ * H_ * HD_;
        const float* wk_l = wk + (size_t)l * D_ * HK_ * HD_;
        const float* wv_l = wv + (size_t)l * D_ * HK_ * HD_;
        const float* wo_l = wo + (size_t)l * H_ * HD_ * D_;
        const float* wg_l = wg + (size_t)l * D_ * FF_;
        const float* wu_l = wu + (size_t)l * D_ * FF_;
        const float* wd_l = wd + (size_t)l * FF_ * D_;

        rmsnorm_kernel<<<TOK_, 256>>>(h, ln1 + l * D_, n);

        gemm_qkv<<<gQKV, 256, GSMEM_BYTES>>>(n, wq_l, wk_l, wv_l, q, k, v);

        qknorm_rope_kernel<<<ropeWarps / 4, 128>>>(q, k, qnw + l * HD_, knw + l * HD_);

        attn_mma_kernel<<<dim3(S_ / 64, H_, B_), 128>>>(
            q, k, v, amask, att, (l & 1) ? WIN_ : -1);

        gemm_tf32<true><<<g1024, 256, GSMEM_BYTES>>>(att, wo_l, h, D_, H_ * HD_);

        rmsnorm_kernel<<<TOK_, 256>>>(h, ln2 + l * D_, n);

        gemm_gateup<<<gGU, 256, GSMEM_BYTES>>>(n, wg_l, wu_l, gate, up);

        int n4 = TOK_ * FF_ / 4;
        silu_mul_kernel<<<(n4 + 255) / 256, 256>>>(gate, up, n4);

        gemm_tf32<true><<<g1024, 256, GSMEM_BYTES>>>(gate, wd_l, h, D_, FF_);
    }

    rmsnorm_kernel<<<TOK_, 256>>>(h, normw, (float*)d_out);
}

// round 9
// speedup vs baseline: 1.2271x; 1.2271x over previous
#include <cuda_runtime.h>
#include <math.h>
#include <float.h>

#define D_    1024
#define H_    16
#define HK_   8
#define HD_   64
#define FF_   3072
#define S_    1024
#define B_    4
#define TOK_  4096   // B*S
#define L_    4
#define WIN_  12

// ---------------- scratch (no allocations allowed) ----------------
__device__ float g_h   [TOK_ * D_];
__device__ float g_n   [TOK_ * D_];
__device__ float g_q   [TOK_ * H_  * HD_];
__device__ float g_k   [TOK_ * HK_ * HD_];
__device__ float g_v   [TOK_ * HK_ * HD_];
__device__ float g_att [TOK_ * H_  * HD_];
__device__ float g_gate[TOK_ * FF_];
__device__ float g_up  [TOK_ * FF_];

// ---------------- helpers ----------------
__device__ __forceinline__ unsigned f2tf(float x) {
    unsigned r;
    asm("cvt.rna.tf32.f32 %0, %1;" : "=r"(r) : "f"(x));
    return r;
}
__device__ __forceinline__ float tfr(float x) { return __uint_as_float(f2tf(x)); }
__device__ __forceinline__ void cpasync16(float* dst_smem, const float* src_gmem) {
    unsigned d = (unsigned)__cvta_generic_to_shared(dst_smem);
    asm volatile("cp.async.cg.shared.global [%0], [%1], 16;"
                 :: "r"(d), "l"(src_gmem));
}
#define CP_COMMIT() asm volatile("cp.async.commit_group;")
#define CP_WAIT0()  asm volatile("cp.async.wait_group 0;")

#define MMA_TF32(acc, a, b)                                              \
    asm volatile(                                                        \
        "mma.sync.aligned.m16n8k8.row.col.f32.tf32.tf32.f32 "            \
        "{%0,%1,%2,%3}, {%4,%5,%6,%7}, {%8,%9}, {%0,%1,%2,%3};"          \
        : "+f"((acc)[0]), "+f"((acc)[1]), "+f"((acc)[2]), "+f"((acc)[3]) \
        : "r"((a)[0]), "r"((a)[1]), "r"((a)[2]), "r"((a)[3]),            \
          "r"((b)[0]), "r"((b)[1]))

// ---------------- rmsnorm over 1024 cols, 1 block per row ----------------
__global__ void rmsnorm_kernel(const float* __restrict__ x,
                               const float* __restrict__ w,
                               float* __restrict__ out) {
    int row = blockIdx.x;
    const float* xr = x + (size_t)row * D_;
    int t = threadIdx.x;               // 256 threads, 4 floats each
    float4 v = *(const float4*)(xr + t * 4);
    float ss = v.x * v.x + v.y * v.y + v.z * v.z + v.w * v.w;
    #pragma unroll
    for (int o = 16; o; o >>= 1) ss += __shfl_xor_sync(0xffffffffu, ss, o);
    __shared__ float sh[8];
    if ((t & 31) == 0) sh[t >> 5] = ss;
    __syncthreads();
    float tot = 0.f;
    #pragma unroll
    for (int i = 0; i < 8; i++) tot += sh[i];
    float scale = rsqrtf(tot * (1.0f / D_) + 1e-6f);
    float4 wv = *(const float4*)(w + t * 4);
    float4 o4;
    o4.x = v.x * scale * wv.x;
    o4.y = v.y * scale * wv.y;
    o4.z = v.z * scale * wv.z;
    o4.w = v.w * scale * wv.w;
    *(float4*)(out + (size_t)row * D_ + t * 4) = o4;
}

// ---------------- TF32 tensor-core GEMM core (R7 config: cp.async, BK=16, 8 warps) ----------------
#define AST_ 20
#define BST_ 136
template <bool ACC>
__device__ __forceinline__ void gemm_core(const float* __restrict__ A,
                                          const float* __restrict__ B,
                                          float* __restrict__ C,
                                          int N, int K, int bx, int by) {
    __shared__ float As[2][128 * AST_];
    __shared__ float Bs[2][16 * BST_];

    int tid = threadIdx.x;
    int lane = tid & 31, wid = tid >> 5;
    int wr = wid >> 2;          // 0..1  (64-row slab)
    int wc = wid & 3;           // 0..3  (32-col slab)
    int tg = lane & 3;          // k index within fragment
    int grp = lane >> 2;        // m/n index within fragment

    const float* Ag = A + (size_t)(by * 128) * K;
    const float* Bg = B + bx * 128;

    int c0 = tid * 2, c1 = tid * 2 + 1;
    int ar0 = c0 >> 2, ac0 = (c0 & 3) << 2;
    int ar1 = c1 >> 2, ac1 = (c1 & 3) << 2;
    int br0 = c0 >> 5, bc0 = (c0 & 31) << 2;
    int br1 = c1 >> 5, bc1 = (c1 & 31) << 2;

    float acc[4][4][4];
    #pragma unroll
    for (int i = 0; i < 4; i++)
        #pragma unroll
        for (int j = 0; j < 4; j++)
            #pragma unroll
            for (int c = 0; c < 4; c++) acc[i][j][c] = 0.f;

    cpasync16(&As[0][ar0 * AST_ + ac0], Ag + (size_t)ar0 * K + ac0);
    cpasync16(&As[0][ar1 * AST_ + ac1], Ag + (size_t)ar1 * K + ac1);
    cpasync16(&Bs[0][br0 * BST_ + bc0], Bg + (size_t)br0 * N + bc0);
    cpasync16(&Bs[0][br1 * BST_ + bc1], Bg + (size_t)br1 * N + bc1);
    CP_COMMIT();

    int nIter = K >> 4;
    for (int it = 0; it < nIter; it++) {
        int cur = it & 1;
        CP_WAIT0();
        __syncthreads();
        if (it + 1 < nIter) {
            int nxt = cur ^ 1;
            int k0n = (it + 1) << 4;
            cpasync16(&As[nxt][ar0 * AST_ + ac0], Ag + (size_t)ar0 * K + k0n + ac0);
            cpasync16(&As[nxt][ar1 * AST_ + ac1], Ag + (size_t)ar1 * K + k0n + ac1);
            cpasync16(&Bs[nxt][br0 * BST_ + bc0], Bg + (size_t)(k0n + br0) * N + bc0);
            cpasync16(&Bs[nxt][br1 * BST_ + bc1], Bg + (size_t)(k0n + br1) * N + bc1);
            CP_COMMIT();
        }

        #pragma unroll
        for (int kk = 0; kk < 16; kk += 8) {
            unsigned afr[4][4], bfr[4][2];
            #pragma unroll
            for (int mt = 0; mt < 4; mt++) {
                int m = wr * 64 + mt * 16 + grp;
                afr[mt][0] = f2tf(As[cur][m * AST_ + kk + tg]);
                afr[mt][1] = f2tf(As[cur][(m + 8) * AST_ + kk + tg]);
                afr[mt][2] = f2tf(As[cur][m * AST_ + kk + tg + 4]);
                afr[mt][3] = f2tf(As[cur][(m + 8) * AST_ + kk + tg + 4]);
            }
            #pragma unroll
            for (int nt = 0; nt < 4; nt++) {
                int n = wc * 32 + nt * 8 + grp;
                bfr[nt][0] = f2tf(Bs[cur][(kk + tg) * BST_ + n]);
                bfr[nt][1] = f2tf(Bs[cur][(kk + tg + 4) * BST_ + n]);
            }
            #pragma unroll
            for (int mt = 0; mt < 4; mt++)
                #pragma unroll
                for (int nt = 0; nt < 4; nt++)
                    MMA_TF32(acc[mt][nt], afr[mt], bfr[nt]);
        }
        __syncthreads();
    }

    #pragma unroll
    for (int mt = 0; mt < 4; mt++) {
        int row0 = by * 128 + wr * 64 + mt * 16 + grp;
        #pragma unroll
        for (int nt = 0; nt < 4; nt++) {
            int col = bx * 128 + wc * 32 + nt * 8 + tg * 2;
            float* p0 = C + (size_t)row0 * N + col;
            float* p1 = C + (size_t)(row0 + 8) * N + col;
            if (ACC) {
                float2 cc0 = *(float2*)p0, cc1 = *(float2*)p1;
                cc0.x += acc[mt][nt][0]; cc0.y += acc[mt][nt][1];
                cc1.x += acc[mt][nt][2]; cc1.y += acc[mt][nt][3];
                *(float2*)p0 = cc0; *(float2*)p1 = cc1;
            } else {
                *(float2*)p0 = make_float2(acc[mt][nt][0], acc[mt][nt][1]);
                *(float2*)p1 = make_float2(acc[mt][nt][2], acc[mt][nt][3]);
            }
        }
    }
}

template <bool ACC>
__global__ void __launch_bounds__(256, 2)
gemm_tf32(const float* __restrict__ A, const float* __restrict__ B,
          float* __restrict__ C, int N, int K) {
    gemm_core<ACC>(A, B, C, N, K, blockIdx.x, blockIdx.y);
}

__global__ void __launch_bounds__(256, 2)
gemm_qkv(const float* __restrict__ A,
         const float* __restrict__ Wq, const float* __restrict__ Wk,
         const float* __restrict__ Wv,
         float* __restrict__ q, float* __restrict__ k, float* __restrict__ v) {
    int bx = blockIdx.x;
    if (bx < 8)       gemm_core<false>(A, Wq, q, 1024, D_, bx,      blockIdx.y);
    else if (bx < 12) gemm_core<false>(A, Wk, k,  512, D_, bx - 8,  blockIdx.y);
    else              gemm_core<false>(A, Wv, v,  512, D_, bx - 12, blockIdx.y);
}

__global__ void __launch_bounds__(256, 2)
gemm_gateup(const float* __restrict__ A,
            const float* __restrict__ Wg, const float* __restrict__ Wu,
            float* __restrict__ gate, float* __restrict__ up) {
    int bx = blockIdx.x;
    if (bx < 24) gemm_core<false>(A, Wg, gate, FF_, D_, bx,      blockIdx.y);
    else         gemm_core<false>(A, Wu, up,   FF_, D_, bx - 24, blockIdx.y);
}

// ---------------- fused per-head rmsnorm + RoPE for q AND k ----------------
#define LOG2_THETA 19.9315685693241741f
__global__ void qknorm_rope_kernel(float* __restrict__ q, float* __restrict__ k,
                                   const float* __restrict__ qw,
                                   const float* __restrict__ kw) {
    int warp = (blockIdx.x * blockDim.x + threadIdx.x) >> 5;
    int lane = threadIdx.x & 31;
    float* p; const float* w; int token;
    if (warp < TOK_ * H_) {
        p = q + (size_t)warp * HD_; w = qw; token = warp / H_;
    } else {
        int w2 = warp - TOK_ * H_;
        p = k + (size_t)w2 * HD_; w = kw; token = w2 / HK_;
    }
    int s = token & (S_ - 1);
    float a = p[lane], b = p[lane + 32];
    float ss = a * a + b * b;
    #pragma unroll
    for (int o = 16; o; o >>= 1) ss += __shfl_xor_sync(0xffffffffu, ss, o);
    float scale = rsqrtf(ss * (1.0f / HD_) + 1e-6f);
    a *= scale * w[lane];
    b *= scale * w[lane + 32];
    float inv = exp2f(-(float)lane * (LOG2_THETA / 32.0f));
    float ang = (float)s * inv;
    float c = cosf(ang), sn = sinf(ang);
    p[lane]      = a * c - b * sn;
    p[lane + 32] = b * c + a * sn;
}

// ---------------- tensor-core flash attention (Q frags hoisted to registers) ----------------
#define QST 68
#define KST 68
#define VST 72
#define PST 36
__global__ void __launch_bounds__(128)
attn_mma_kernel(const float* __restrict__ q, const float* __restrict__ k,
                const float* __restrict__ v, const int* __restrict__ amask,
                float* __restrict__ out, int win) {
    __shared__ float Qs[64 * QST];
    __shared__ float Ks[32 * KST];
    __shared__ float Vs[32 * VST];
    __shared__ float Ps[64 * PST];
    __shared__ float Mk[32];

    int b = blockIdx.z, h = blockIdx.y;
    int q0 = blockIdx.x * 64;
    int kh = h >> 1;
    int tid = threadIdx.x;
    int lane = tid & 31, wid = tid >> 5;
    int tg = lane & 3, grp = lane >> 2;
    int m0 = wid * 16;
    int qpos0 = q0 + m0 + grp;
    int qpos1 = qpos0 + 8;

    for (int i = tid; i < 64 * 16; i += 128) {
        int r = i >> 4, c4 = (i & 15) << 2;
        float4 f = *(const float4*)(q + (size_t)(b * S_ + q0 + r) * (H_ * HD_) + h * HD_ + c4);
        Qs[r * QST + c4 + 0] = tfr(f.x);
        Qs[r * QST + c4 + 1] = tfr(f.y);
        Qs[r * QST + c4 + 2] = tfr(f.z);
        Qs[r * QST + c4 + 3] = tfr(f.w);
    }
    __syncthreads();

    // hoist Q fragments (invariant over K-tiles): 8 k-slices x 4 regs
    unsigned qfr[8][4];
    #pragma unroll
    for (int s8 = 0; s8 < 8; s8++) {
        int k8 = s8 * 8;
        qfr[s8][0] = __float_as_uint(Qs[(m0 + grp) * QST + k8 + tg]);
        qfr[s8][1] = __float_as_uint(Qs[(m0 + grp + 8) * QST + k8 + tg]);
        qfr[s8][2] = __float_as_uint(Qs[(m0 + grp) * QST + k8 + tg + 4]);
        qfr[s8][3] = __float_as_uint(Qs[(m0 + grp + 8) * QST + k8 + tg + 4]);
    }

    float oacc[8][4];
    #pragma unroll
    for (int i = 0; i < 8; i++)
        #pragma unroll
        for (int j = 0; j < 4; j++) oacc[i][j] = 0.f;
    float mr0 = -1e30f, mr1 = -1e30f, l0 = 0.f, l1 = 0.f;

    int kt_lo = 0, kt_hi = (S_ / 32) - 1;
    if (win >= 0) {
        int lo = q0 - win; if (lo < 0) lo = 0;
        int hi = q0 + 63 + win; if (hi > S_ - 1) hi = S_ - 1;
        kt_lo = lo >> 5; kt_hi = hi >> 5;
    }
    const float scale = 0.125f;

    for (int kt = kt_lo; kt <= kt_hi; kt++) {
        for (int i = tid; i < 32 * 16; i += 128) {
            int r = i >> 4, c4 = (i & 15) << 2;
            size_t off = (size_t)(b * S_ + kt * 32 + r) * (HK_ * HD_) + kh * HD_ + c4;
            float4 fk = *(const float4*)(k + off);
            float4 fv = *(const float4*)(v + off);
            Ks[r * KST + c4 + 0] = tfr(fk.x);
            Ks[r * KST + c4 + 1] = tfr(fk.y);
            Ks[r * KST + c4 + 2] = tfr(fk.z);
            Ks[r * KST + c4 + 3] = tfr(fk.w);
            Vs[r * VST + c4 + 0] = tfr(fv.x);
            Vs[r * VST + c4 + 1] = tfr(fv.y);
            Vs[r * VST + c4 + 2] = tfr(fv.z);
            Vs[r * VST + c4 + 3] = tfr(fv.w);
        }
        if (tid < 32)
            Mk[tid] = (amask[b * S_ + kt * 32 + tid] != 0) ? 0.f : -1e30f;
        __syncthreads();

        float sc[4][4];
        #pragma unroll
        for (int i = 0; i < 4; i++)
            #pragma unroll
            for (int j = 0; j < 4; j++) sc[i][j] = 0.f;
        #pragma unroll
        for (int s8 = 0; s8 < 8; s8++) {
            int k8 = s8 * 8;
            #pragma unroll
            for (int nt = 0; nt < 4; nt++) {
                unsigned bb[2];
                bb[0] = __float_as_uint(Ks[(nt * 8 + grp) * KST + k8 + tg]);
                bb[1] = __float_as_uint(Ks[(nt * 8 + grp) * KST + k8 + tg + 4]);
                MMA_TF32(sc[nt], qfr[s8], bb);
            }
        }

        float v0[8], v1[8];
        #pragma unroll
        for (int nt = 0; nt < 4; nt++) {
            int kc0 = nt * 8 + 2 * tg, kc1 = kc0 + 1;
            int kp0 = kt * 32 + kc0, kp1 = kt * 32 + kc1;
            float mk0 = Mk[kc0], mk1 = Mk[kc1];
            float a0 = sc[nt][0] * scale + mk0;
            float a1 = sc[nt][1] * scale + mk1;
            float b0 = sc[nt][2] * scale + mk0;
            float b1 = sc[nt][3] * scale + mk1;
            if (win >= 0) {
                if (abs(qpos0 - kp0) > win) a0 = -1e30f;
                if (abs(qpos0 - kp1) > win) a1 = -1e30f;
                if (abs(qpos1 - kp0) > win) b0 = -1e30f;
                if (abs(qpos1 - kp1) > win) b1 = -1e30f;
            }
            v0[nt * 2] = a0; v0[nt * 2 + 1] = a1;
            v1[nt * 2] = b0; v1[nt * 2 + 1] = b1;
        }
        float tm0 = -1e30f, tm1 = -1e30f;
        #pragma unroll
        for (int j = 0; j < 8; j++) { tm0 = fmaxf(tm0, v0[j]); tm1 = fmaxf(tm1, v1[j]); }
        tm0 = fmaxf(tm0, __shfl_xor_sync(0xffffffffu, tm0, 1));
        tm0 = fmaxf(tm0, __shfl_xor_sync(0xffffffffu, tm0, 2));
        tm1 = fmaxf(tm1, __shfl_xor_sync(0xffffffffu, tm1, 1));
        tm1 = fmaxf(tm1, __shfl_xor_sync(0xffffffffu, tm1, 2));
        float nm0 = fmaxf(mr0, tm0), nm1 = fmaxf(mr1, tm1);
        float al0 = __expf(mr0 - nm0), al1 = __expf(mr1 - nm1);
        mr0 = nm0; mr1 = nm1;
        float ps0 = 0.f, ps1 = 0.f;
        #pragma unroll
        for (int nt = 0; nt < 4; nt++) {
            float p00 = __expf(v0[nt * 2]     - nm0);
            float p01 = __expf(v0[nt * 2 + 1] - nm0);
            float p10 = __expf(v1[nt * 2]     - nm1);
            float p11 = __expf(v1[nt * 2 + 1] - nm1);
            ps0 += p00 + p01; ps1 += p10 + p11;
            int col = nt * 8 + 2 * tg;
            *(float2*)&Ps[(m0 + grp) * PST + col]     = make_float2(tfr(p00), tfr(p01));
            *(float2*)&Ps[(m0 + grp + 8) * PST + col] = make_float2(tfr(p10), tfr(p11));
        }
        ps0 += __shfl_xor_sync(0xffffffffu, ps0, 1);
        ps0 += __shfl_xor_sync(0xffffffffu, ps0, 2);
        ps1 += __shfl_xor_sync(0xffffffffu, ps1, 1);
        ps1 += __shfl_xor_sync(0xffffffffu, ps1, 2);
        l0 = l0 * al0 + ps0;
        l1 = l1 * al1 + ps1;
        #pragma unroll
        for (int nt = 0; nt < 8; nt++) {
            oacc[nt][0] *= al0; oacc[nt][1] *= al0;
            oacc[nt][2] *= al1; oacc[nt][3] *= al1;
        }
        __syncwarp();

        #pragma unroll
        for (int k8 = 0; k8 < 32; k8 += 8) {
            unsigned a[4];
            a[0] = __float_as_uint(Ps[(m0 + grp) * PST + k8 + tg]);
            a[1] = __float_as_uint(Ps[(m0 + grp + 8) * PST + k8 + tg]);
            a[2] = __float_as_uint(Ps[(m0 + grp) * PST + k8 + tg + 4]);
            a[3] = __float_as_uint(Ps[(m0 + grp + 8) * PST + k8 + tg + 4]);
            #pragma unroll
            for (int nt = 0; nt < 8; nt++) {
                unsigned bb[2];
                bb[0] = __float_as_uint(Vs[(k8 + tg) * VST + nt * 8 + grp]);
                bb[1] = __float_as_uint(Vs[(k8 + tg + 4) * VST + nt * 8 + grp]);
                MMA_TF32(oacc[nt], a, bb);
            }
        }
        __syncthreads();
    }

    float il0 = 1.0f / l0, il1 = 1.0f / l1;
    #pragma unroll
    for (int nt = 0; nt < 8; nt++) {
        int col = h * HD_ + nt * 8 + 2 * tg;
        float* p0 = out + (size_t)(b * S_ + qpos0) * (H_ * HD_) + col;
        float* p1 = out + (size_t)(b * S_ + qpos1) * (H_ * HD_) + col;
        *(float2*)p0 = make_float2(oacc[nt][0] * il0, oacc[nt][1] * il0);
        *(float2*)p1 = make_float2(oacc[nt][2] * il1, oacc[nt][3] * il1);
    }
}

// ---------------- SwiGLU elementwise (vectorized x4) ----------------
__global__ void silu_mul_kernel(float* __restrict__ gate,
                                const float* __restrict__ up, int n4) {
    int i = blockIdx.x * blockDim.x + threadIdx.x;
    if (i < n4) {
        float4 g = *(float4*)(gate + i * 4);
        float4 u = *(const float4*)(up + i * 4);
        g.x = g.x / (1.0f + __expf(-g.x)) * u.x;
        g.y = g.y / (1.0f + __expf(-g.y)) * u.y;
        g.z = g.z / (1.0f + __expf(-g.z)) * u.z;
        g.w = g.w / (1.0f + __expf(-g.w)) * u.w;
        *(float4*)(gate + i * 4) = g;
    }
}

// ---------------- host orchestration ----------------
extern "C" void kernel_launch(void* const* d_in, const int* in_sizes, int n_in,
                              void* d_out, int out_size) {
    const float* x      = (const float*)d_in[0];
    const float* wq     = (const float*)d_in[1];
    const float* wk     = (const float*)d_in[2];
    const float* wv     = (const float*)d_in[3];
    const float* wo     = (const float*)d_in[4];
    const float* qnw    = (const float*)d_in[5];
    const float* knw    = (const float*)d_in[6];
    const float* ln1    = (const float*)d_in[7];
    const float* ln2    = (const float*)d_in[8];
    const float* wg     = (const float*)d_in[9];
    const float* wu     = (const float*)d_in[10];
    const float* wd     = (const float*)d_in[11];
    const float* normw  = (const float*)d_in[12];
    const int*   amask  = (const int*)d_in[13];

    float *h, *n, *q, *k, *v, *att, *gate, *up;
    cudaGetSymbolAddress((void**)&h,    g_h);
    cudaGetSymbolAddress((void**)&n,    g_n);
    cudaGetSymbolAddress((void**)&q,    g_q);
    cudaGetSymbolAddress((void**)&k,    g_k);
    cudaGetSymbolAddress((void**)&v,    g_v);
    cudaGetSymbolAddress((void**)&att,  g_att);
    cudaGetSymbolAddress((void**)&gate, g_gate);
    cudaGetSymbolAddress((void**)&up,   g_up);

    cudaMemcpyAsync(h, x, (size_t)TOK_ * D_ * sizeof(float),
                    cudaMemcpyDeviceToDevice, 0);

    dim3 gQKV (16, TOK_ / 128);              // 512 blocks
    dim3 gGU  (48, TOK_ / 128);              // 1536 blocks
    dim3 g1024(D_ / 128, TOK_ / 128);        // 256 blocks
    int ropeWarps = TOK_ * (H_ + HK_);       // 98304 warps

    for (int l = 0; l < L_; l++) {
        const float* wq_l = wq + (size_t)l * D_ * H_ * HD_;
        const float* wk_l = wk + (size_t)l * D_ * HK_ * HD_;
        const float* wv_l = wv + (size_t)l * D_ * HK_ * HD_;
        const float* wo_l = wo + (size_t)l * H_ * HD_ * D_;
        const float* wg_l = wg + (size_t)l * D_ * FF_;
        const float* wu_l = wu + (size_t)l * D_ * FF_;
        const float* wd_l = wd + (size_t)l * FF_ * D_;

        rmsnorm_kernel<<<TOK_, 256>>>(h, ln1 + l * D_, n);

        gemm_qkv<<<gQKV, 256>>>(n, wq_l, wk_l, wv_l, q, k, v);

        qknorm_rope_kernel<<<ropeWarps / 4, 128>>>(q, k, qnw + l * HD_, knw + l * HD_);

        attn_mma_kernel<<<dim3(S_ / 64, H_, B_), 128>>>(
            q, k, v, amask, att, (l & 1) ? WIN_ : -1);

        gemm_tf32<true><<<g1024, 256>>>(att, wo_l, h, D_, H_ * HD_);

        rmsnorm_kernel<<<TOK_, 256>>>(h, ln2 + l * D_, n);

        gemm_gateup<<<gGU, 256>>>(n, wg_l, wu_l, gate, up);

        int n4 = TOK_ * FF_ / 4;
        silu_mul_kernel<<<(n4 + 255) / 256, 256>>>(gate, up, n4);

        gemm_tf32<true><<<g1024, 256>>>(gate, wd_l, h, D_, FF_);
    }

    rmsnorm_kernel<<<TOK_, 256>>>(h, normw, (float*)d_out);
}